// round 1
// baseline (speedup 1.0000x reference)
#include <cuda_runtime.h>

// Problem constants (fixed shapes per reference): x [B, N, C], weight [C, N]
#define Ndim 196
#define Cdim 768
#define Bdim 256

#define TC   64          // channels per block
#define KG   4           // k-groups (KG * TC = 256 threads)
#define KPT  49          // k values per thread (Ndim / KG)
#define KT   7           // k register tile (KPT = 7 * 7)
#define NQ   (Ndim / 4)  // 49 float4 chunks along n
#define PAD  204         // row pitch (multiple of 4, conflict-free for LDS.128)

#define SMEM_BYTES (2 * TC * PAD * 4)

// Transform matrices, precomputed each launch (graph-capturable, deterministic).
// g_D[k][n] = 2 * cos(pi * k * (2n+1) / (2N))           (DCT-II)
// g_E[n][k] = c_k * cos(pi * k * (2n+1) / (2N))         (inverse), c_0=1/(2N), c_k=1/N
__device__ float g_D[Ndim * Ndim];
__device__ float g_E[Ndim * Ndim];

__global__ void setup_kernel() {
    int k = blockIdx.x;   // 0..195
    int n = threadIdx.x;  // 0..195
    int r = (k * (2 * n + 1)) % (4 * Ndim);   // exact integer range reduction
    float c = cospif((float)r / (float)(2 * Ndim));
    g_D[k * Ndim + n] = 2.0f * c;
    float ck = (k == 0) ? (0.5f / (float)Ndim) : (1.0f / (float)Ndim);
    g_E[n * Ndim + k] = ck * c;
}

__global__ __launch_bounds__(256, 2)
void dct_filter_kernel(const float* __restrict__ x,
                       const float* __restrict__ w,
                       float* __restrict__ y) {
    extern __shared__ float smem[];
    float* xs = smem;             // [TC][PAD]  x transposed: xs[cl][n]
    float* ts = smem + TC * PAD;  // [TC][PAD]  intermediate: ts[cl][k]

    const int b   = blockIdx.y;
    const int c0  = blockIdx.x * TC;
    const int tid = threadIdx.x;

    // ---- Phase 1: load x[b, :, c0..c0+63] into SMEM, transposed ----
    const float* xb = x + (size_t)b * Ndim * Cdim + c0;
    for (int i = tid; i < Ndim * TC; i += 256) {
        int n  = i >> 6;
        int cl = i & 63;
        xs[cl * PAD + n] = xb[n * Cdim + cl];
    }
    __syncthreads();

    const int cl = tid & 63;
    const int kg = tid >> 6;
    const float4* xrow = (const float4*)(xs + cl * PAD);

    // ---- Phase 2: ts[cl][k] = w[c0+cl, k] * sum_n D[k][n] * xs[cl][n] ----
    const float* wrow = w + (size_t)(c0 + cl) * Ndim;
    #pragma unroll 1
    for (int jt = 0; jt < KPT / KT; jt++) {
        const int k0 = kg * KPT + jt * KT;
        float acc[KT];
        #pragma unroll
        for (int t = 0; t < KT; t++) acc[t] = 0.0f;

        for (int q = 0; q < NQ; q++) {
            float4 xv = xrow[q];
            #pragma unroll
            for (int t = 0; t < KT; t++) {
                float4 d = ((const float4*)(g_D + (size_t)(k0 + t) * Ndim))[q];
                acc[t] += d.x * xv.x;
                acc[t] += d.y * xv.y;
                acc[t] += d.z * xv.z;
                acc[t] += d.w * xv.w;
            }
        }
        #pragma unroll
        for (int t = 0; t < KT; t++) {
            int k = k0 + t;
            ts[cl * PAD + k] = acc[t] * wrow[k];
        }
    }
    __syncthreads();

    // ---- Phase 3: y[b, n, c0+cl] = sum_k E[n][k] * ts[cl][k] ----
    float* yb = y + (size_t)b * Ndim * Cdim + c0;
    const float4* trow = (const float4*)(ts + cl * PAD);
    #pragma unroll 1
    for (int jt = 0; jt < KPT / KT; jt++) {
        const int n0 = kg * KPT + jt * KT;
        float acc[KT];
        #pragma unroll
        for (int t = 0; t < KT; t++) acc[t] = 0.0f;

        for (int q = 0; q < NQ; q++) {
            float4 tv = trow[q];
            #pragma unroll
            for (int t = 0; t < KT; t++) {
                float4 e = ((const float4*)(g_E + (size_t)(n0 + t) * Ndim))[q];
                acc[t] += e.x * tv.x;
                acc[t] += e.y * tv.y;
                acc[t] += e.z * tv.z;
                acc[t] += e.w * tv.w;
            }
        }
        #pragma unroll
        for (int t = 0; t < KT; t++) {
            yb[(size_t)(n0 + t) * Cdim + cl] = acc[t];
        }
    }
}

extern "C" void kernel_launch(void* const* d_in, const int* in_sizes, int n_in,
                              void* d_out, int out_size) {
    const float* x = (const float*)d_in[0];   // [B, N, C] fp32
    const float* w = (const float*)d_in[1];   // [C, N]    fp32
    float* y = (float*)d_out;                 // [B, N, C] fp32

    cudaFuncSetAttribute(dct_filter_kernel,
                         cudaFuncAttributeMaxDynamicSharedMemorySize, SMEM_BYTES);

    setup_kernel<<<Ndim, Ndim>>>();

    dim3 grid(Cdim / TC, Bdim);
    dct_filter_kernel<<<grid, 256, SMEM_BYTES>>>(x, w, y);
}

// round 3
// speedup vs baseline: 4.4265x; 4.4265x over previous
#include <cuda_runtime.h>
#include <cuda_fp16.h>
#include <stdint.h>

// Shapes (fixed): x [B=256, N=196, C=768], weight [C=768, N=196], y [B, N, C]
#define NREAL  196
#define CDIM   768
#define BDIM   256
#define KPAD   208     // contraction dim padded to 13*16
#define KSTEPS 13
#define MC     64      // channels per CTA
#define CBLKS  12      // 768 / 64
#define BGROUPS 12
#define GRID   144     // CBLKS * BGROUPS (persistent)

#define APITCH 216     // halfs; pitch % 16 == 8 -> conflict-free ldmatrix
#define BPITCH 232     // halfs; pitch % 16 == 8 -> conflict-free ldmatrix
#define WPITCH 200

#define SM_A    0                       // 64 * 216 * 2   = 27,648
#define SM_B1   27648                   // 208 * 232 * 2  = 96,512
#define SM_B2   124160                  // 96,512
#define SM_STG  220672                  // 28 * 68 * 4    = 7,616
#define SMEM_TOTAL 228288               // <= 232,448 (227KB cap)

// Precomputed operands (setup kernels fill these every launch; deterministic).
__device__ __align__(16) __half g_B1[KPAD * BPITCH];   // B1[n][k] = 2*cos(pi*k*(2n+1)/(2N))
__device__ __align__(16) __half g_B2[KPAD * BPITCH];   // B2[k][n] = c_k*cos(pi*k*(2n+1)/(2N))
__device__ __align__(16) __half g_wh[CDIM * WPITCH];   // fp16 copy of weight, zero-padded

// ---------------- helpers ----------------
__device__ __forceinline__ uint32_t smem_u32(const void* p) {
    uint32_t a;
    asm("{ .reg .u64 t; cvta.to.shared.u64 t, %1; cvt.u32.u64 %0, t; }" : "=r"(a) : "l"(p));
    return a;
}
__device__ __forceinline__ void ldsm_x4(uint32_t addr, uint32_t& r0, uint32_t& r1,
                                        uint32_t& r2, uint32_t& r3) {
    asm volatile("ldmatrix.sync.aligned.m8n8.x4.shared.b16 {%0,%1,%2,%3}, [%4];"
                 : "=r"(r0), "=r"(r1), "=r"(r2), "=r"(r3) : "r"(addr));
}
__device__ __forceinline__ void ldsm_x4t(uint32_t addr, uint32_t& r0, uint32_t& r1,
                                         uint32_t& r2, uint32_t& r3) {
    asm volatile("ldmatrix.sync.aligned.m8n8.x4.trans.shared.b16 {%0,%1,%2,%3}, [%4];"
                 : "=r"(r0), "=r"(r1), "=r"(r2), "=r"(r3) : "r"(addr));
}
__device__ __forceinline__ void ldsm_x2t(uint32_t addr, uint32_t& r0, uint32_t& r1) {
    asm volatile("ldmatrix.sync.aligned.m8n8.x2.trans.shared.b16 {%0,%1}, [%2];"
                 : "=r"(r0), "=r"(r1) : "r"(addr));
}
__device__ __forceinline__ void mma16816(float c[4], uint32_t a0, uint32_t a1, uint32_t a2,
                                         uint32_t a3, uint32_t b0, uint32_t b1) {
    asm volatile(
        "mma.sync.aligned.m16n8k16.row.col.f32.f16.f16.f32 "
        "{%0,%1,%2,%3}, {%4,%5,%6,%7}, {%8,%9}, {%0,%1,%2,%3};"
        : "+f"(c[0]), "+f"(c[1]), "+f"(c[2]), "+f"(c[3])
        : "r"(a0), "r"(a1), "r"(a2), "r"(a3), "r"(b0), "r"(b1));
}

// Warp tile: M=32 (2 m-tiles), N=56 (7 n-tiles), contraction KPAD=208.
__device__ __forceinline__ void gemm_tile(uint32_t sA, uint32_t sB, int mw, int nw,
                                          int lane, float acc[2][7][4]) {
    #pragma unroll
    for (int mt = 0; mt < 2; mt++)
        #pragma unroll
        for (int nt = 0; nt < 7; nt++)
            #pragma unroll
            for (int j = 0; j < 4; j++) acc[mt][nt][j] = 0.f;

    const int lr = lane & 15;
    const int lc = lane >> 4;
    const uint32_t aBase = sA + (uint32_t)((mw * 32 + lr) * (APITCH * 2)) + (uint32_t)(lc * 16);
    const uint32_t bBase = sB + (uint32_t)(lr * (BPITCH * 2)) +
                           (uint32_t)((nw * 56 + lc * 8) * 2);
    const uint32_t bBase2 = sB + (uint32_t)(lr * (BPITCH * 2)) + (uint32_t)((nw * 56 + 48) * 2);

    #pragma unroll 1
    for (int ks = 0; ks < KSTEPS; ks++) {
        const uint32_t ko = (uint32_t)(ks * 32);                    // 16 halfs
        const uint32_t kro = (uint32_t)(ks * 16 * (BPITCH * 2));    // 16 B rows
        uint32_t a[2][4];
        #pragma unroll
        for (int mt = 0; mt < 2; mt++)
            ldsm_x4(aBase + (uint32_t)(mt * 16 * (APITCH * 2)) + ko,
                    a[mt][0], a[mt][1], a[mt][2], a[mt][3]);
        uint32_t bf[7][2];
        #pragma unroll
        for (int p = 0; p < 3; p++)
            ldsm_x4t(bBase + kro + (uint32_t)(p * 32),
                     bf[2 * p][0], bf[2 * p][1], bf[2 * p + 1][0], bf[2 * p + 1][1]);
        ldsm_x2t(bBase2 + kro, bf[6][0], bf[6][1]);

        #pragma unroll
        for (int mt = 0; mt < 2; mt++)
            #pragma unroll
            for (int nt = 0; nt < 7; nt++)
                mma16816(acc[mt][nt], a[mt][0], a[mt][1], a[mt][2], a[mt][3],
                         bf[nt][0], bf[nt][1]);
    }
}

// ---------------- setup kernels ----------------
__global__ void setup_B() {
    int row = blockIdx.x;    // 0..207
    int col = threadIdx.x;   // 0..231
    float v1 = 0.f, v2 = 0.f;
    if (row < NREAL && col < NREAL) {
        // B1[n=row][k=col]
        int r1 = (col * (2 * row + 1)) % (4 * NREAL);
        v1 = 2.f * cospif((float)r1 / (float)(2 * NREAL));
        // B2[k=row][n=col]
        int r2 = (row * (2 * col + 1)) % (4 * NREAL);
        float ck = (row == 0) ? (0.5f / (float)NREAL) : (1.0f / (float)NREAL);
        v2 = ck * cospif((float)r2 / (float)(2 * NREAL));
    }
    g_B1[row * BPITCH + col] = __float2half_rn(v1);
    g_B2[row * BPITCH + col] = __float2half_rn(v2);
}

__global__ void setup_wh(const float* __restrict__ w) {
    int c = blockIdx.x, k = threadIdx.x;   // 768 x 200
    float v = (k < NREAL) ? w[(size_t)c * NREAL + k] : 0.f;
    g_wh[c * WPITCH + k] = __float2half_rn(v);
}

// ---------------- main persistent kernel ----------------
__global__ __launch_bounds__(256, 1)
void dct_mma_kernel(const float* __restrict__ x, float* __restrict__ y) {
    extern __shared__ __align__(16) char smem[];
    const uint32_t sb = smem_u32(smem);
    const int tid = threadIdx.x;
    const int lane = tid & 31, wid = tid >> 5;
    const int mw = wid & 1, nw = wid >> 1;
    const int grp = lane >> 2, t4 = lane & 3;

    const int chan0 = (blockIdx.x % CBLKS) * MC;
    const int bstart = blockIdx.x / CBLKS;

    // Resident B1/B2 (loaded once), zeroed A tile (padding stays zero forever).
    {
        const float4* s1 = (const float4*)g_B1;
        const float4* s2 = (const float4*)g_B2;
        float4* d1 = (float4*)(smem + SM_B1);
        float4* d2 = (float4*)(smem + SM_B2);
        for (int i = tid; i < (KPAD * BPITCH * 2) / 16; i += 256) { d1[i] = s1[i]; d2[i] = s2[i]; }
        float4 z = make_float4(0.f, 0.f, 0.f, 0.f);
        float4* a4 = (float4*)(smem + SM_A);
        for (int i = tid; i < (MC * APITCH * 2) / 16; i += 256) a4[i] = z;
    }
    __syncthreads();

    float* stg = (float*)(smem + SM_STG);

    for (int b = bstart; b < BDIM; b += BGROUPS) {
        // ---- phase X: x[b, :, chan0..+63] -> A[c][n] fp16 (7 blocks of 28 n) ----
        for (int blk = 0; blk < 7; blk++) {
            const float* xp = x + ((size_t)b * NREAL + blk * 28) * CDIM + chan0;
            for (int i = tid; i < 448; i += 256) {
                int n = i >> 4, c4 = i & 15;
                *(float4*)(stg + n * 68 + c4 * 4) =
                    *(const float4*)(xp + (size_t)n * CDIM + c4 * 4);
            }
            __syncthreads();
            const int cc = tid & 63;
            for (int np = tid >> 6; np < 14; np += 4) {
                __half2 h = __floats2half2_rn(stg[2 * np * 68 + cc], stg[(2 * np + 1) * 68 + cc]);
                *(uint32_t*)(smem + SM_A + cc * (APITCH * 2) + (blk * 28 + 2 * np) * 2) =
                    *(uint32_t*)&h;
            }
            __syncthreads();
        }

        float acc[2][7][4];

        // ---- GEMM1: C1[c][k] = A1 x B1 ----
        gemm_tile(sb + SM_A, sb + SM_B1, mw, nw, lane, acc);
        __syncthreads();   // all A1 reads done before overwrite

        // ---- mid: A2[c][k] = fp16(C1 * w) in place ----
        #pragma unroll
        for (int mt = 0; mt < 2; mt++) {
            #pragma unroll
            for (int nt = 0; nt < 7; nt++) {
                int col = nw * 56 + nt * 8 + 2 * t4;
                if (col < NREAL) {
                    int r0 = mw * 32 + mt * 16 + grp;
                    int r1 = r0 + 8;
                    float2 w0 = __half22float2(*(const __half2*)&g_wh[(chan0 + r0) * WPITCH + col]);
                    float2 w1 = __half22float2(*(const __half2*)&g_wh[(chan0 + r1) * WPITCH + col]);
                    __half2 h0 = __floats2half2_rn(acc[mt][nt][0] * w0.x, acc[mt][nt][1] * w0.y);
                    __half2 h1 = __floats2half2_rn(acc[mt][nt][2] * w1.x, acc[mt][nt][3] * w1.y);
                    *(uint32_t*)(smem + SM_A + r0 * (APITCH * 2) + col * 2) = *(uint32_t*)&h0;
                    *(uint32_t*)(smem + SM_A + r1 * (APITCH * 2) + col * 2) = *(uint32_t*)&h1;
                }
            }
        }
        __syncthreads();

        // ---- GEMM2: C2[c][n] = A2 x B2 ----
        gemm_tile(sb + SM_A, sb + SM_B2, mw, nw, lane, acc);

        // ---- epilogue: y[b, n, chan0 + c] = C2[c][n] ----
        float* yb = y + (size_t)b * NREAL * CDIM + chan0;
        #pragma unroll
        for (int mt = 0; mt < 2; mt++) {
            #pragma unroll
            for (int nt = 0; nt < 7; nt++) {
                int col = nw * 56 + nt * 8 + 2 * t4;
                if (col < NREAL) {
                    int r0 = mw * 32 + mt * 16 + grp;
                    int r1 = r0 + 8;
                    yb[(size_t)col * CDIM + r0]       = acc[mt][nt][0];
                    yb[(size_t)(col + 1) * CDIM + r0] = acc[mt][nt][1];
                    yb[(size_t)col * CDIM + r1]       = acc[mt][nt][2];
                    yb[(size_t)(col + 1) * CDIM + r1] = acc[mt][nt][3];
                }
            }
        }
        __syncthreads();   // A2 reads done before next tile's x-phase
    }
}

extern "C" void kernel_launch(void* const* d_in, const int* in_sizes, int n_in,
                              void* d_out, int out_size) {
    const float* x = (const float*)d_in[0];  // [B, N, C] fp32
    const float* w = (const float*)d_in[1];  // [C, N]    fp32
    float* y = (float*)d_out;                // [B, N, C] fp32

    cudaFuncSetAttribute(dct_mma_kernel,
                         cudaFuncAttributeMaxDynamicSharedMemorySize, SMEM_TOTAL);

    setup_B<<<KPAD, BPITCH>>>();
    setup_wh<<<CDIM, WPITCH>>>(w);
    dct_mma_kernel<<<GRID, 256, SMEM_TOTAL>>>(x, y);
}

// round 4
// speedup vs baseline: 11.3661x; 2.5677x over previous
#include <cuda_runtime.h>
#include <cuda_fp16.h>
#include <stdint.h>

// Shapes (fixed): x [B=256, N=196, C=768], weight [C=768, N=196], y [B, N, C]
#define NREAL  196
#define CDIM   768
#define BDIM   256
#define KPAD   208        // n and k_dct both padded to 13*16
#define KSTEPS 13
#define MC     128        // channels per tile
#define NTILES 1536       // 256 batches * 6 channel-blocks
#define GRID   148        // persistent

#define XPITCH 136        // halfs (272B rows; conflict-free for trans ldmatrix)
#define BPITCH 216        // halfs (432B rows; conflict-free both orientations)
#define TPITCH 216
#define WPITCH 200

#define SM_B1  0                          // 208*216*2 = 89,856
#define SM_X   89856                      // 208*136*2 = 56,576
#define SM_T   146432                     // 128*216*2 = 55,296
#define SMEM_TOTAL 201728                 // <= 232,448

// Precomputed operands.
__device__ __align__(16) __half g_B1[KPAD * BPITCH];  // B1[n][k] = 2*cos(pi*k*(2n+1)/(2N)), 0-padded
__device__ __align__(16) __half g_wh[CDIM * WPITCH];  // fp16 weight, 0-padded cols 196..199

// ---------------- helpers ----------------
__device__ __forceinline__ uint32_t smem_u32(const void* p) {
    uint32_t a;
    asm("{ .reg .u64 t; cvta.to.shared.u64 t, %1; cvt.u32.u64 %0, t; }" : "=r"(a) : "l"(p));
    return a;
}
__device__ __forceinline__ void ldsm_x4(uint32_t addr, uint32_t& r0, uint32_t& r1,
                                        uint32_t& r2, uint32_t& r3) {
    asm volatile("ldmatrix.sync.aligned.m8n8.x4.shared.b16 {%0,%1,%2,%3}, [%4];"
                 : "=r"(r0), "=r"(r1), "=r"(r2), "=r"(r3) : "r"(addr));
}
__device__ __forceinline__ void ldsm_x2(uint32_t addr, uint32_t& r0, uint32_t& r1) {
    asm volatile("ldmatrix.sync.aligned.m8n8.x2.shared.b16 {%0,%1}, [%2];"
                 : "=r"(r0), "=r"(r1) : "r"(addr));
}
__device__ __forceinline__ void ldsm_x4t(uint32_t addr, uint32_t& r0, uint32_t& r1,
                                         uint32_t& r2, uint32_t& r3) {
    asm volatile("ldmatrix.sync.aligned.m8n8.x4.trans.shared.b16 {%0,%1,%2,%3}, [%4];"
                 : "=r"(r0), "=r"(r1), "=r"(r2), "=r"(r3) : "r"(addr));
}
__device__ __forceinline__ void ldsm_x2t(uint32_t addr, uint32_t& r0, uint32_t& r1) {
    asm volatile("ldmatrix.sync.aligned.m8n8.x2.trans.shared.b16 {%0,%1}, [%2];"
                 : "=r"(r0), "=r"(r1) : "r"(addr));
}
__device__ __forceinline__ void mma16816(float c[4], uint32_t a0, uint32_t a1, uint32_t a2,
                                         uint32_t a3, uint32_t b0, uint32_t b1) {
    asm volatile(
        "mma.sync.aligned.m16n8k16.row.col.f32.f16.f16.f32 "
        "{%0,%1,%2,%3}, {%4,%5,%6,%7}, {%8,%9}, {%0,%1,%2,%3};"
        : "+f"(c[0]), "+f"(c[1]), "+f"(c[2]), "+f"(c[3])
        : "r"(a0), "r"(a1), "r"(a2), "r"(a3), "r"(b0), "r"(b1));
}

// ---------------- setup kernels ----------------
__global__ void setup_B1() {
    int n = blockIdx.x;    // 0..207
    int k = threadIdx.x;   // 0..215
    float v = 0.f;
    if (n < NREAL && k < NREAL) {
        int r = (k * (2 * n + 1)) % (4 * NREAL);
        v = 2.f * cospif((float)r / (float)(2 * NREAL));
    }
    g_B1[n * BPITCH + k] = __float2half_rn(v);
}
__global__ void setup_wh(const float* __restrict__ w) {
    int c = blockIdx.x, k = threadIdx.x;   // 768 x 200
    float v = (k < NREAL) ? w[(size_t)c * NREAL + k] : 0.f;
    g_wh[c * WPITCH + k] = __float2half_rn(v);
}

// ---------------- main persistent kernel ----------------
__global__ __launch_bounds__(256, 1)
void dct_mma_kernel(const float* __restrict__ x, float* __restrict__ y) {
    extern __shared__ __align__(16) char smem[];
    const uint32_t sb = smem_u32(smem);
    const uint32_t sX = sb + SM_X, sB = sb + SM_B1, sT = sb + SM_T;
    const int tid = threadIdx.x;
    const int lane = tid & 31, wid = tid >> 5;
    const int mw = wid & 3;              // 4 M-groups (channels), 32 each
    const int nw = wid >> 2;             // 2 N-groups, 104 each
    const int cw = mw * 32;
    const int nbase = nw * 104;

    // lane-derived constants
    const int lr  = lane & 15;
    const int lc  = lane >> 4;
    const int kk  = (lane & 7) + ((lane >> 4) << 3);   // trans/A & B row select
    const int g8  = ((lane >> 3) & 1) << 3;            // 0 or 8
    const int grp = lane >> 2;                          // c-frag row
    const int q2  = (lane & 3) << 1;                    // c-frag col pair

    // One-time: copy B1 to SMEM, zero X (incl. pad rows).
    {
        const float4* s1 = (const float4*)g_B1;
        float4* d1 = (float4*)(smem + SM_B1);
        for (int i = tid; i < (KPAD * BPITCH * 2) / 16; i += 256) d1[i] = s1[i];
        float4 z = make_float4(0.f, 0.f, 0.f, 0.f);
        float4* xz = (float4*)(smem + SM_X);
        for (int i = tid; i < (KPAD * XPITCH * 2) / 16; i += 256) xz[i] = z;
    }
    __syncthreads();

    for (int t = blockIdx.x; t < NTILES; t += GRID) {
        const int cb = t % 6;
        const int b  = t / 6;
        const int c0 = cb * MC;

        // ---- load x[b, 0..195, c0..c0+127] -> X[n][c] fp16 (coalesced) ----
        {
            const float4* xp = (const float4*)(x + ((size_t)b * NREAL) * CDIM + c0);
            const int rowq = CDIM / 4;   // 192 float4 per gmem row
            for (int i = tid; i < NREAL * 32; i += 256) {
                int n = i >> 5, c4 = i & 31;
                float4 v = xp[n * rowq + c4];
                __half2 h0 = __floats2half2_rn(v.x, v.y);
                __half2 h1 = __floats2half2_rn(v.z, v.w);
                uint2 u = make_uint2(*(uint32_t*)&h0, *(uint32_t*)&h1);
                *(uint2*)(smem + SM_X + n * (XPITCH * 2) + c4 * 8) = u;
            }
        }
        __syncthreads();

        float acc[2][13][4];
        #pragma unroll
        for (int mt = 0; mt < 2; mt++)
            #pragma unroll
            for (int nt = 0; nt < 13; nt++)
                #pragma unroll
                for (int j = 0; j < 4; j++) acc[mt][nt][j] = 0.f;

        // ---- GEMM1: C1[c][kdct] = X^T x B1  (A trans-loaded from X[n][c]) ----
        {
            const uint32_t aB = sX + (uint32_t)(kk * (XPITCH * 2)) + (uint32_t)((cw + g8) * 2);
            const uint32_t bB = sB + (uint32_t)(lr * (BPITCH * 2)) + (uint32_t)((nbase + lc * 8) * 2);
            const uint32_t bB2 = sB + (uint32_t)(lr * (BPITCH * 2)) + (uint32_t)((nbase + 96) * 2);
            #pragma unroll 1
            for (int ks = 0; ks < KSTEPS; ks++) {
                const uint32_t kro = (uint32_t)(ks * 16 * (XPITCH * 2));
                const uint32_t krb = (uint32_t)(ks * 16 * (BPITCH * 2));
                uint32_t a[2][4];
                #pragma unroll
                for (int mt = 0; mt < 2; mt++)
                    ldsm_x4t(aB + kro + (uint32_t)(mt * 32),
                             a[mt][0], a[mt][1], a[mt][2], a[mt][3]);
                uint32_t bf[13][2];
                #pragma unroll
                for (int p = 0; p < 6; p++)
                    ldsm_x4t(bB + krb + (uint32_t)(p * 32),
                             bf[2 * p][0], bf[2 * p][1], bf[2 * p + 1][0], bf[2 * p + 1][1]);
                ldsm_x2t(bB2 + krb, bf[12][0], bf[12][1]);
                #pragma unroll
                for (int mt = 0; mt < 2; mt++)
                    #pragma unroll
                    for (int nt = 0; nt < 13; nt++)
                        mma16816(acc[mt][nt], a[mt][0], a[mt][1], a[mt][2], a[mt][3],
                                 bf[nt][0], bf[nt][1]);
            }
        }
        __syncthreads();

        // ---- mid: T[c][k] = fp16( C1 * w[c][k] * s_k ), s_k = c_k/2 ----
        #pragma unroll
        for (int mt = 0; mt < 2; mt++) {
            const int r0 = cw + mt * 16 + grp;
            const int r1 = r0 + 8;
            #pragma unroll
            for (int nt = 0; nt < 13; nt++) {
                const int col = nbase + nt * 8 + q2;
                const int colw = (col < NREAL) ? col : 0;
                float2 w0 = __half22float2(*(const __half2*)&g_wh[(c0 + r0) * WPITCH + colw]);
                float2 w1 = __half22float2(*(const __half2*)&g_wh[(c0 + r1) * WPITCH + colw]);
                float s0 = (col == 0) ? (0.25f / NREAL)
                         : ((col < NREAL) ? (0.5f / NREAL) : 0.f);
                float s1 = (col + 1 < NREAL) ? (0.5f / NREAL) : 0.f;
                __half2 h0 = __floats2half2_rn(acc[mt][nt][0] * w0.x * s0,
                                               acc[mt][nt][1] * w0.y * s1);
                __half2 h1 = __floats2half2_rn(acc[mt][nt][2] * w1.x * s0,
                                               acc[mt][nt][3] * w1.y * s1);
                *(uint32_t*)(smem + SM_T + r0 * (TPITCH * 2) + col * 2) = *(uint32_t*)&h0;
                *(uint32_t*)(smem + SM_T + r1 * (TPITCH * 2) + col * 2) = *(uint32_t*)&h1;
            }
        }
        __syncthreads();

        #pragma unroll
        for (int mt = 0; mt < 2; mt++)
            #pragma unroll
            for (int nt = 0; nt < 13; nt++)
                #pragma unroll
                for (int j = 0; j < 4; j++) acc[mt][nt][j] = 0.f;

        // ---- GEMM2: C2[c][n] = T x B1^T (A non-trans from T[c][k], B non-trans from B1[n][k]) ----
        {
            const uint32_t aB = sT + (uint32_t)((cw + lr) * (TPITCH * 2)) + (uint32_t)(lc * 16);
            const uint32_t bB = sB + (uint32_t)((nbase + kk) * (BPITCH * 2)) + (uint32_t)(g8 * 2);
            const uint32_t bB2 = sB + (uint32_t)((nbase + 96 + (lane & 7)) * (BPITCH * 2)) +
                                 (uint32_t)(g8 * 2);
            #pragma unroll 1
            for (int ks = 0; ks < KSTEPS; ks++) {
                const uint32_t ko = (uint32_t)(ks * 32);
                uint32_t a[2][4];
                #pragma unroll
                for (int mt = 0; mt < 2; mt++)
                    ldsm_x4(aB + (uint32_t)(mt * 16 * (TPITCH * 2)) + ko,
                            a[mt][0], a[mt][1], a[mt][2], a[mt][3]);
                uint32_t bf[13][2];
                #pragma unroll
                for (int p = 0; p < 6; p++)
                    ldsm_x4(bB + (uint32_t)(p * 16 * (BPITCH * 2)) + ko,
                            bf[2 * p][0], bf[2 * p][1], bf[2 * p + 1][0], bf[2 * p + 1][1]);
                ldsm_x2(bB2 + ko, bf[12][0], bf[12][1]);
                #pragma unroll
                for (int mt = 0; mt < 2; mt++)
                    #pragma unroll
                    for (int nt = 0; nt < 13; nt++)
                        mma16816(acc[mt][nt], a[mt][0], a[mt][1], a[mt][2], a[mt][3],
                                 bf[nt][0], bf[nt][1]);
            }
        }

        // ---- epilogue: y[b, n, c0 + c] = C2[c][n] ----
        {
            float* yb = y + (size_t)b * NREAL * CDIM + c0;
            #pragma unroll
            for (int mt = 0; mt < 2; mt++) {
                const int r0 = cw + mt * 16 + grp;
                const int r1 = r0 + 8;
                #pragma unroll
                for (int nt = 0; nt < 13; nt++) {
                    const int ncol = nbase + nt * 8 + q2;
                    if (ncol < NREAL) {
                        yb[(size_t)ncol * CDIM + r0]       = acc[mt][nt][0];
                        yb[(size_t)(ncol + 1) * CDIM + r0] = acc[mt][nt][1];
                        yb[(size_t)ncol * CDIM + r1]       = acc[mt][nt][2];
                        yb[(size_t)(ncol + 1) * CDIM + r1] = acc[mt][nt][3];
                    }
                }
            }
        }
        __syncthreads();   // T reads done before next tile's mid-phase; X reads long done
    }
}

extern "C" void kernel_launch(void* const* d_in, const int* in_sizes, int n_in,
                              void* d_out, int out_size) {
    const float* x = (const float*)d_in[0];  // [B, N, C] fp32
    const float* w = (const float*)d_in[1];  // [C, N]    fp32
    float* y = (float*)d_out;                // [B, N, C] fp32

    cudaFuncSetAttribute(dct_mma_kernel,
                         cudaFuncAttributeMaxDynamicSharedMemorySize, SMEM_TOTAL);

    setup_B1<<<KPAD, BPITCH>>>();
    setup_wh<<<CDIM, WPITCH>>>(w);
    dct_mma_kernel<<<GRID, 256, SMEM_TOTAL>>>(x, y);
}